// round 10
// baseline (speedup 1.0000x reference)
#include <cuda_runtime.h>
#include <cuda_bf16.h>
#include <cstdint>

#define BATCH 8
#define CIN   32
#define COUT  64
#define HW    (512 * 512)
#define NPIX  (BATCH * HW)
#define TILE  128
#define NT    128

#define WPITCH 80            // W rows: 40 bf16 = 80B (B-frag LDS bank-perfect)
#define DPITCH 528           // D rows: 132 floats (epilogue STS bank = 8t+g+c, distinct)

// smem byte offsets
#define D_OFF   0            // D: 64 * 528 = 33792
#define WHI_OFF 33792        // 64 * 80 = 5120
#define WLO_OFF (WHI_OFF + 5120)
#define BS_OFF  (WLO_OFF + 5120)     // 256
#define SMEM_TOT (BS_OFF + 256)      // 44288 < 48KB static

__device__ __forceinline__ void mma16816(float* c, const uint32_t* a, const uint32_t* b) {
    asm volatile(
        "mma.sync.aligned.m16n8k16.row.col.f32.bf16.bf16.f32 "
        "{%0,%1,%2,%3}, {%4,%5,%6,%7}, {%8,%9}, {%0,%1,%2,%3};"
        : "+f"(c[0]), "+f"(c[1]), "+f"(c[2]), "+f"(c[3])
        : "r"(a[0]), "r"(a[1]), "r"(a[2]), "r"(a[3]), "r"(b[0]), "r"(b[1]));
}

__device__ __forceinline__ uint32_t pack_bf16(__nv_bfloat16 e0, __nv_bfloat16 e1) {
    __nv_bfloat162 v; v.x = e0; v.y = e1;
    return *(uint32_t*)&v;
}
__device__ __forceinline__ uint32_t pack_hi(float a, float b) {
    return pack_bf16(__float2bfloat16(a), __float2bfloat16(b));
}
__device__ __forceinline__ uint32_t pack_lo(float a, float b) {
    __nv_bfloat16 ha = __float2bfloat16(a);
    __nv_bfloat16 hb = __float2bfloat16(b);
    return pack_bf16(__float2bfloat16(a - __bfloat162float(ha)),
                     __float2bfloat16(b - __bfloat162float(hb)));
}

static __device__ __forceinline__ uint32_t smem_u32(const void* p) {
    uint32_t a;
    asm("{ .reg .u64 t; cvta.to.shared.u64 t, %1; cvt.u32.u64 %0, t; }" : "=r"(a) : "l"(p));
    return a;
}

#define BULK_S2G(gdst, ssrc, by) \
    asm volatile("cp.async.bulk.global.shared::cta.bulk_group [%0], [%1], %2;" \
                 :: "l"(gdst), "r"(ssrc), "r"(by) : "memory")

__global__ void __launch_bounds__(NT, 4)
spconv_mma_kernel(const float* __restrict__ x,
                  const float* __restrict__ Wg,
                  const float* __restrict__ bias,
                  float* __restrict__ out) {
    __shared__ __align__(16) char smc[SMEM_TOT];
    const uint32_t sb = smem_u32(smc);

    const int tid = threadIdx.x;
    const long long p0 = (long long)blockIdx.x * TILE;
    const int b   = (int)(p0 / HW);
    const int hw0 = (int)(p0 % HW);

    // ---- stage W^T hi/lo in smem (pitch 80B) + bias ----
    {
        const int o    = tid >> 1;
        const int half = tid & 1;
        uint32_t hp[8], lp[8];
        #pragma unroll
        for (int j = 0; j < 8; ++j) {
            int ch = half * 16 + 2 * j;
            float w0 = Wg[ch * COUT + o];
            float w1 = Wg[(ch + 1) * COUT + o];
            hp[j] = pack_hi(w0, w1);
            lp[j] = pack_lo(w0, w1);
        }
        char* wh = smc + WHI_OFF + o * WPITCH + half * 32;
        char* wl = smc + WLO_OFF + o * WPITCH + half * 32;
        ((uint4*)wh)[0] = make_uint4(hp[0], hp[1], hp[2], hp[3]);
        ((uint4*)wh)[1] = make_uint4(hp[4], hp[5], hp[6], hp[7]);
        ((uint4*)wl)[0] = make_uint4(lp[0], lp[1], lp[2], lp[3]);
        ((uint4*)wl)[1] = make_uint4(lp[4], lp[5], lp[6], lp[7]);
    }
    if (tid < COUT) ((float*)(smc + BS_OFF))[tid] = bias[tid];

    // ---- x direct from gmem in fragment layout: 32 independent LDG.32 ----
    const int w = tid >> 5;
    const int l = tid & 31;
    const int g = l >> 2;     // groupID
    const int t = l & 3;      // thread-in-group
    const int rowbase = 32 * w;

    const float* xb = x + (long long)b * CIN * HW + hw0 + rowbase + g
                        + (long long)(2 * t) * HW;

    float v[4][8];   // r -> pixel rowbase+g+8r ; c -> channel 2t+dd[c]
    #pragma unroll
    for (int r = 0; r < 4; ++r) {
        #pragma unroll
        for (int c = 0; c < 8; ++c) {
            const int dd = (c & 1) + ((c >> 1) & 1) * 8 + (c >> 2) * 16;  // 0,1,8,9,16,17,24,25
            v[r][c] = __ldg(xb + (long long)dd * HW + 8 * r);
        }
    }

    // ---- per-pixel activity via t-quad shfl OR ----
    uint32_t msk[4];
    #pragma unroll
    for (int r = 0; r < 4; ++r) {
        uint32_t m = 0u;
        #pragma unroll
        for (int c = 0; c < 8; ++c) m |= __float_as_uint(v[r][c]) & 0x7FFFFFFFu;
        m |= __shfl_xor_sync(0xFFFFFFFFu, m, 1);
        m |= __shfl_xor_sync(0xFFFFFFFFu, m, 2);
        msk[r] = m;
    }

    // ---- bf16 hi/lo fragments ----
    uint32_t ah[2][2][4], al[2][2][4];
    #pragma unroll
    for (int m = 0; m < 2; ++m) {
        #pragma unroll
        for (int k = 0; k < 2; ++k) {
            ah[m][k][0] = pack_hi(v[2*m][4*k],     v[2*m][4*k+1]);
            ah[m][k][1] = pack_hi(v[2*m+1][4*k],   v[2*m+1][4*k+1]);
            ah[m][k][2] = pack_hi(v[2*m][4*k+2],   v[2*m][4*k+3]);
            ah[m][k][3] = pack_hi(v[2*m+1][4*k+2], v[2*m+1][4*k+3]);
            al[m][k][0] = pack_lo(v[2*m][4*k],     v[2*m][4*k+1]);
            al[m][k][1] = pack_lo(v[2*m+1][4*k],   v[2*m+1][4*k+1]);
            al[m][k][2] = pack_lo(v[2*m][4*k+2],   v[2*m][4*k+3]);
            al[m][k][3] = pack_lo(v[2*m+1][4*k+2], v[2*m+1][4*k+3]);
        }
    }

    float acc[2][8][4];
    #pragma unroll
    for (int m = 0; m < 2; ++m)
        #pragma unroll
        for (int n = 0; n < 8; ++n)
            #pragma unroll
            for (int r = 0; r < 4; ++r) acc[m][n][r] = 0.0f;

    __syncthreads();   // W smem ready

    // ---- mainloop: 3-term bf16 split over K=32 ----
    const char* WH = smc + WHI_OFF;
    const char* WL = smc + WLO_OFF;
    #pragma unroll
    for (int k = 0; k < 2; ++k) {
        const int cb = 32 * k + 4 * t;
        #pragma unroll
        for (int nb = 0; nb < 2; ++nb) {
            uint32_t bh[4][2], bl[4][2];
            #pragma unroll
            for (int nn = 0; nn < 4; ++nn) {
                int o = 8 * (4 * nb + nn) + g;
                int off = o * WPITCH + cb;
                bh[nn][0] = *(const uint32_t*)(WH + off);
                bh[nn][1] = *(const uint32_t*)(WH + off + 16);
                bl[nn][0] = *(const uint32_t*)(WL + off);
                bl[nn][1] = *(const uint32_t*)(WL + off + 16);
            }
            #pragma unroll
            for (int nn = 0; nn < 4; ++nn)
                #pragma unroll
                for (int m = 0; m < 2; ++m)
                    mma16816(acc[m][4 * nb + nn], ah[m][k], bh[nn]);
            #pragma unroll
            for (int nn = 0; nn < 4; ++nn)
                #pragma unroll
                for (int m = 0; m < 2; ++m)
                    mma16816(acc[m][4 * nb + nn], ah[m][k], bl[nn]);
            #pragma unroll
            for (int nn = 0; nn < 4; ++nn)
                #pragma unroll
                for (int m = 0; m < 2; ++m)
                    mma16816(acc[m][4 * nb + nn], al[m][k], bh[nn]);
        }
    }

    // ---- epilogue: masked bias-add -> smem D[o][px], conflict-free STS ----
    const float* bs = (const float*)(smc + BS_OFF);
    char* Dt = smc + D_OFF;
    #pragma unroll
    for (int m = 0; m < 2; ++m) {
        int px0 = rowbase + 16 * m + g;
        int px1 = px0 + 8;
        bool A0 = msk[2 * m]     != 0u;
        bool A1 = msk[2 * m + 1] != 0u;
        #pragma unroll
        for (int n = 0; n < 8; ++n) {
            int o = 8 * n + 2 * t;
            float2 bv = *(const float2*)(bs + o);
            *(float*)(Dt + o * DPITCH + px0 * 4)       = A0 ? acc[m][n][0] + bv.x : 0.0f;
            *(float*)(Dt + (o + 1) * DPITCH + px0 * 4) = A0 ? acc[m][n][1] + bv.y : 0.0f;
            *(float*)(Dt + o * DPITCH + px1 * 4)       = A1 ? acc[m][n][2] + bv.x : 0.0f;
            *(float*)(Dt + (o + 1) * DPITCH + px1 * 4) = A1 ? acc[m][n][3] + bv.y : 0.0f;
        }
    }

    asm volatile("fence.proxy.async.shared::cta;" ::: "memory");
    __syncthreads();

    // ---- bulk-store 64 output rows (512B each): no LSU wavefronts ----
    if (tid < COUT) {
        float* gdst = out + (long long)b * COUT * HW + (long long)tid * HW + hw0;
        BULK_S2G(gdst, sb + D_OFF + tid * DPITCH, TILE * 4);
        asm volatile("cp.async.bulk.commit_group;" ::: "memory");
        asm volatile("cp.async.bulk.wait_group 0;" ::: "memory");
    }
}

extern "C" void kernel_launch(void* const* d_in, const int* in_sizes, int n_in,
                              void* d_out, int out_size) {
    const float* x  = (const float*)d_in[0];
    const float* Wg = (const float*)d_in[1];
    const float* bi = (const float*)d_in[2];
    float* out = (float*)d_out;

    const int grid = NPIX / TILE;   // 16384
    spconv_mma_kernel<<<grid, NT>>>(x, Wg, bi, out);
}

// round 11
// speedup vs baseline: 1.2764x; 1.2764x over previous
#include <cuda_runtime.h>
#include <cuda_bf16.h>
#include <cstdint>

#define BATCH 8
#define CIN   32
#define COUT  64
#define HW    (512 * 512)
#define NPIX  (BATCH * HW)
#define TILE  128
#define NT    128

#define XPITCHB 528        // x rows: 132 floats; frag LDS bank = 8t+g (+c), all distinct
#define WPITCHB 96         // W rows: pair-interleaved, LDS.64 bank set 24g+2t distinct/phase

// smem byte offsets
#define XS_OFF  0                      // 32 * 528 = 16896
#define WHI_OFF 16896                  // 64 * 96 = 6144
#define WLO_OFF (WHI_OFF + 6144)
#define BS_OFF  (WLO_OFF + 6144)       // 256
#define SMEM_TOT (BS_OFF + 256)        // 29440 < 48KB static

__device__ __forceinline__ void mma16816(float* c, const uint32_t* a, const uint32_t* b) {
    asm volatile(
        "mma.sync.aligned.m16n8k16.row.col.f32.bf16.bf16.f32 "
        "{%0,%1,%2,%3}, {%4,%5,%6,%7}, {%8,%9}, {%0,%1,%2,%3};"
        : "+f"(c[0]), "+f"(c[1]), "+f"(c[2]), "+f"(c[3])
        : "r"(a[0]), "r"(a[1]), "r"(a[2]), "r"(a[3]), "r"(b[0]), "r"(b[1]));
}

__device__ __forceinline__ uint32_t pack_bf16(__nv_bfloat16 e0, __nv_bfloat16 e1) {
    __nv_bfloat162 v; v.x = e0; v.y = e1;
    return *(uint32_t*)&v;
}
__device__ __forceinline__ uint32_t pack_hi(float a, float b) {
    return pack_bf16(__float2bfloat16(a), __float2bfloat16(b));
}
__device__ __forceinline__ uint32_t pack_lo(float a, float b) {
    __nv_bfloat16 ha = __float2bfloat16(a);
    __nv_bfloat16 hb = __float2bfloat16(b);
    return pack_bf16(__float2bfloat16(a - __bfloat162float(ha)),
                     __float2bfloat16(b - __bfloat162float(hb)));
}

static __device__ __forceinline__ uint32_t smem_u32(const void* p) {
    uint32_t a;
    asm("{ .reg .u64 t; cvta.to.shared.u64 t, %1; cvt.u32.u64 %0, t; }" : "=r"(a) : "l"(p));
    return a;
}

#define CP_ASYNC16(dst, src) \
    asm volatile("cp.async.ca.shared.global [%0], [%1], 16;" :: "r"(dst), "l"(src) : "memory")

__global__ void __launch_bounds__(NT, 4)
spconv_mma_kernel(const float* __restrict__ x,
                  const float* __restrict__ Wg,
                  const float* __restrict__ bias,
                  float* __restrict__ out) {
    __shared__ __align__(16) char smc[SMEM_TOT];
    const uint32_t sb = smem_u32(smc);

    const int tid = threadIdx.x;
    const long long p0 = (long long)blockIdx.x * TILE;
    const int b   = (int)(p0 / HW);
    const int hw0 = (int)(p0 % HW);
    const float* xb = x + (long long)b * CIN * HW + hw0;

    // ---- issue x staging FIRST: 8 coalesced cp.async.128 per thread ----
    #pragma unroll
    for (int it = 0; it < 8; ++it) {
        int i  = tid + it * NT;
        int ch = i >> 5;     // channel
        int q  = i & 31;     // pixel quad
        CP_ASYNC16(sb + XS_OFF + ch * XPITCHB + q * 16, xb + (long long)ch * HW + 4 * q);
    }
    asm volatile("cp.async.commit_group;" ::: "memory");

    // ---- stage W^T hi/lo, pair-interleaved for LDS.64 b-frags (overlaps cp.async) ----
    {
        const int o = tid >> 1;
        const int k = tid & 1;     // k-half: channels 16k..16k+15
        #pragma unroll
        for (int t = 0; t < 4; ++t) {
            int ch0 = 2 * t + 16 * k;      // pair (ch0, ch0+1)
            int ch1 = ch0 + 8;             // pair (ch1, ch1+1)
            float a0 = Wg[ch0 * COUT + o], a1 = Wg[(ch0 + 1) * COUT + o];
            float b0 = Wg[ch1 * COUT + o], b1 = Wg[(ch1 + 1) * COUT + o];
            uint32_t h0 = pack_hi(a0, a1), h1 = pack_hi(b0, b1);
            uint32_t l0 = pack_lo(a0, a1), l1 = pack_lo(b0, b1);
            int off = o * WPITCHB + k * 32 + t * 8;
            *(uint2*)(smc + WHI_OFF + off) = make_uint2(h0, h1);
            *(uint2*)(smc + WLO_OFF + off) = make_uint2(l0, l1);
        }
    }
    if (tid < COUT) ((float*)(smc + BS_OFF))[tid] = bias[tid];

    const int w = tid >> 5;
    const int l = tid & 31;
    const int g = l >> 2;     // groupID
    const int t = l & 3;      // thread-in-group
    const int rowbase = 32 * w;

    // ---- wait x staging, sync (also publishes W smem) ----
    asm volatile("cp.async.wait_group 0;" ::: "memory");
    __syncthreads();

    // ---- x fragments from smem: 32 conflict-free LDS.32 ----
    float v[4][8];   // r -> pixel rowbase+g+8r ; c -> channel 2t+dd[c]
    const char* xsm = smc + XS_OFF;
    #pragma unroll
    for (int r = 0; r < 4; ++r) {
        #pragma unroll
        for (int c = 0; c < 8; ++c) {
            const int dd = (c & 1) + ((c >> 1) & 1) * 8 + (c >> 2) * 16;  // 0,1,8,9,16,17,24,25
            const int ch = 2 * t + dd;
            v[r][c] = *(const float*)(xsm + ch * XPITCHB + (rowbase + g + 8 * r) * 4);
        }
    }

    // ---- per-pixel activity via t-quad shfl OR ----
    uint32_t msk[4];
    #pragma unroll
    for (int r = 0; r < 4; ++r) {
        uint32_t m = 0u;
        #pragma unroll
        for (int c = 0; c < 8; ++c) m |= __float_as_uint(v[r][c]) & 0x7FFFFFFFu;
        m |= __shfl_xor_sync(0xFFFFFFFFu, m, 1);
        m |= __shfl_xor_sync(0xFFFFFFFFu, m, 2);
        msk[r] = m;
    }

    // ---- bf16 hi/lo A fragments ----
    uint32_t ah[2][2][4], al[2][2][4];
    #pragma unroll
    for (int m = 0; m < 2; ++m) {
        #pragma unroll
        for (int k = 0; k < 2; ++k) {
            ah[m][k][0] = pack_hi(v[2*m][4*k],     v[2*m][4*k+1]);
            ah[m][k][1] = pack_hi(v[2*m+1][4*k],   v[2*m+1][4*k+1]);
            ah[m][k][2] = pack_hi(v[2*m][4*k+2],   v[2*m][4*k+3]);
            ah[m][k][3] = pack_hi(v[2*m+1][4*k+2], v[2*m+1][4*k+3]);
            al[m][k][0] = pack_lo(v[2*m][4*k],     v[2*m][4*k+1]);
            al[m][k][1] = pack_lo(v[2*m+1][4*k],   v[2*m+1][4*k+1]);
            al[m][k][2] = pack_lo(v[2*m][4*k+2],   v[2*m][4*k+3]);
            al[m][k][3] = pack_lo(v[2*m+1][4*k+2], v[2*m+1][4*k+3]);
        }
    }

    float acc[2][8][4];
    #pragma unroll
    for (int m = 0; m < 2; ++m)
        #pragma unroll
        for (int n = 0; n < 8; ++n)
            #pragma unroll
            for (int r = 0; r < 4; ++r) acc[m][n][r] = 0.0f;

    // ---- mainloop: 3-term bf16 split; b-frags via single LDS.64 each ----
    const char* WH = smc + WHI_OFF;
    const char* WL = smc + WLO_OFF;
    #pragma unroll
    for (int k = 0; k < 2; ++k) {
        #pragma unroll
        for (int nb = 0; nb < 2; ++nb) {
            uint32_t bh[4][2], bl[4][2];
            #pragma unroll
            for (int nn = 0; nn < 4; ++nn) {
                int o = 8 * (4 * nb + nn) + g;
                int off = o * WPITCHB + k * 32 + t * 8;
                uint2 hv = *(const uint2*)(WH + off);
                uint2 lv = *(const uint2*)(WL + off);
                bh[nn][0] = hv.x; bh[nn][1] = hv.y;
                bl[nn][0] = lv.x; bl[nn][1] = lv.y;
            }
            #pragma unroll
            for (int nn = 0; nn < 4; ++nn)
                #pragma unroll
                for (int m = 0; m < 2; ++m)
                    mma16816(acc[m][4 * nb + nn], ah[m][k], bh[nn]);
            #pragma unroll
            for (int nn = 0; nn < 4; ++nn)
                #pragma unroll
                for (int m = 0; m < 2; ++m)
                    mma16816(acc[m][4 * nb + nn], ah[m][k], bl[nn]);
            #pragma unroll
            for (int nn = 0; nn < 4; ++nn)
                #pragma unroll
                for (int m = 0; m < 2; ++m)
                    mma16816(acc[m][4 * nb + nn], al[m][k], bh[nn]);
        }
    }

    // ---- epilogue: R8's direct masked STG (best-known store path) ----
    const float* bs = (const float*)(smc + BS_OFF);
    float* ob = out + (long long)b * COUT * HW + hw0;
    #pragma unroll
    for (int m = 0; m < 2; ++m) {
        int px0 = rowbase + 16 * m + g;
        int px1 = px0 + 8;
        bool A0 = msk[2 * m]     != 0u;
        bool A1 = msk[2 * m + 1] != 0u;
        #pragma unroll
        for (int n = 0; n < 8; ++n) {
            int o = 8 * n + 2 * t;
            float2 bv = *(const float2*)(bs + o);
            ob[(long long)o * HW + px0]       = A0 ? acc[m][n][0] + bv.x : 0.0f;
            ob[(long long)(o + 1) * HW + px0] = A0 ? acc[m][n][1] + bv.y : 0.0f;
            ob[(long long)o * HW + px1]       = A1 ? acc[m][n][2] + bv.x : 0.0f;
            ob[(long long)(o + 1) * HW + px1] = A1 ? acc[m][n][3] + bv.y : 0.0f;
        }
    }
}

extern "C" void kernel_launch(void* const* d_in, const int* in_sizes, int n_in,
                              void* d_out, int out_size) {
    const float* x  = (const float*)d_in[0];
    const float* Wg = (const float*)d_in[1];
    const float* bi = (const float*)d_in[2];
    float* out = (float*)d_out;

    const int grid = NPIX / TILE;   // 16384
    spconv_mma_kernel<<<grid, NT>>>(x, Wg, bi, out);
}